// round 11
// baseline (speedup 1.0000x reference)
#include <cuda_runtime.h>
#include <math.h>
#include <stdint.h>

#define BB 64
#define TT 512
#define II 512
#define HH 1024
#define OO 512
#define MM 64
#define PP 1024
#define G3 3072
#define NB 148
#define NT 1024
#define SKX 68                  // smem row stride (floats)
#define BUFF ((64 + 256) * SKX) // floats per stage buffer = 21760

__device__ __align__(16) float g_h[2][BB * HH];
__device__ __align__(16) float g_xin[BB * II];
__device__ __align__(16) float g_gi[8][BB * G3];
__device__ __align__(16) float g_gh[8][BB * G3];
__device__ __align__(16) float g_cp[8][BB * OO];
__device__ __align__(16) float g_memT[MM * PP];
__device__ volatile unsigned g_gen;
__device__ unsigned g_cnt;

static __device__ __forceinline__ uint32_t smem_u32(const void* p)
{
    uint32_t a;
    asm("{ .reg .u64 t; cvta.to.shared.u64 t, %1; cvt.u32.u64 %0, t; }"
        : "=r"(a) : "l"(p));
    return a;
}

static __device__ __forceinline__ void cp16(uint32_t dst, const void* src)
{
    asm volatile("cp.async.cg.shared.global [%0], [%1], 16;"
                 :: "r"(dst), "l"(src));
}

static __device__ __forceinline__ void ffma2(unsigned long long& d,
                                             unsigned long long a,
                                             unsigned long long b)
{
    asm("fma.rn.f32x2 %0, %1, %2, %0;" : "+l"(d) : "l"(a), "l"(b));
}

__device__ __forceinline__ void gsync()
{
    __syncthreads();
    __threadfence();
    if (threadIdx.x == 0) {
        unsigned my = g_gen;
        if (atomicAdd(&g_cnt, 1u) == NB - 1u) {
            atomicExch(&g_cnt, 0u);
            __threadfence();
            g_gen = my + 1u;
        } else {
            while (g_gen == my) { __nanosleep(64); }
        }
    }
    __syncthreads();
    __threadfence();
}

// ---------------------------------------------------------------------------
// 64(batch) x 256(cols) x (nch*64) GEMM partial. 1024 threads, 4x4/thread,
// FFMA2 inner loop, cp.async double-buffered staging, ONE sync per chunk.
//   outp[b*ldo + n0+n] = sum_k X[b*ldx + k] * W[(n)*ldw + k]   (W pre-offset)
// ---------------------------------------------------------------------------
static __device__ void gemm256(
    const float* __restrict__ W, int ldw,
    const float* __restrict__ X, int ldx,
    int nch, float* __restrict__ outp, int ldo, int n0,
    const float* smf, uint32_t sb)
{
    const int tid = threadIdx.x;
    const int ty  = tid & 15;       // batch rows ty + {0,16,32,48}
    const int tx  = tid >> 4;       // cols tx + {0,64,128,192}
    const int xr  = tid >> 4;       // staging row 0..63
    const int xk  = (tid & 15) << 2;

    // issue chunk 0
    {
        cp16(sb + (uint32_t)(xr * SKX + xk) * 4u, X + (size_t)xr * ldx + xk);
        uint32_t wo = sb + 64u * SKX * 4u;
        #pragma unroll
        for (int q = 0; q < 4; q++) {
            int idx = tid + q * NT, r = idx >> 4, kk = (idx & 15) << 2;
            cp16(wo + (uint32_t)(r * SKX + kk) * 4u, W + (size_t)r * ldw + kk);
        }
        asm volatile("cp.async.commit_group;" ::: "memory");
    }

    unsigned long long acc[4][4];
    #pragma unroll
    for (int i = 0; i < 4; i++)
        #pragma unroll
        for (int j = 0; j < 4; j++) acc[i][j] = 0ull;

    for (int c = 0; c < nch; c++) {
        asm volatile("cp.async.wait_group 0;" ::: "memory");
        __syncthreads();

        if (c + 1 < nch) {
            uint32_t bo = sb + (uint32_t)((c + 1) & 1) * (BUFF * 4u);
            int k0 = (c + 1) << 6;
            cp16(bo + (uint32_t)(xr * SKX + xk) * 4u,
                 X + (size_t)xr * ldx + k0 + xk);
            uint32_t wo = bo + 64u * SKX * 4u;
            #pragma unroll
            for (int q = 0; q < 4; q++) {
                int idx = tid + q * NT, r = idx >> 4, kk = (idx & 15) << 2;
                cp16(wo + (uint32_t)(r * SKX + kk) * 4u,
                     W + (size_t)r * ldw + k0 + kk);
            }
            asm volatile("cp.async.commit_group;" ::: "memory");
        }

        const float* xs = smf + (c & 1) * BUFF;
        const float* ws = xs + 64 * SKX;
        const float* x0 = xs + ty * SKX;
        const float* w0 = ws + tx * SKX;
        #pragma unroll
        for (int k4 = 0; k4 < 16; k4++) {
            float4 xv0 = *(const float4*)(x0 + k4 * 4);
            float4 xv1 = *(const float4*)(x0 + 16 * SKX + k4 * 4);
            float4 xv2 = *(const float4*)(x0 + 32 * SKX + k4 * 4);
            float4 xv3 = *(const float4*)(x0 + 48 * SKX + k4 * 4);
            #pragma unroll
            for (int j = 0; j < 4; j++) {
                float4 wv = *(const float4*)(w0 + j * 64 * SKX + k4 * 4);
                unsigned long long wlo = *(unsigned long long*)&wv.x;
                unsigned long long whi = *(unsigned long long*)&wv.z;
                ffma2(acc[0][j], *(unsigned long long*)&xv0.x, wlo);
                ffma2(acc[0][j], *(unsigned long long*)&xv0.z, whi);
                ffma2(acc[1][j], *(unsigned long long*)&xv1.x, wlo);
                ffma2(acc[1][j], *(unsigned long long*)&xv1.z, whi);
                ffma2(acc[2][j], *(unsigned long long*)&xv2.x, wlo);
                ffma2(acc[2][j], *(unsigned long long*)&xv2.z, whi);
                ffma2(acc[3][j], *(unsigned long long*)&xv3.x, wlo);
                ffma2(acc[3][j], *(unsigned long long*)&xv3.z, whi);
            }
        }
    }

    #pragma unroll
    for (int i = 0; i < 4; i++) {
        float* orow = outp + (size_t)(ty + i * 16) * ldo + n0 + tx;
        #pragma unroll
        for (int j = 0; j < 4; j++) {
            float2 v = *(float2*)&acc[i][j];
            orow[j * 64] = v.x + v.y;
        }
    }
}

// ---------------------------------------------------------------------------
// Phase A for one batch row (1024 threads): content read + softmax + relu.
// ---------------------------------------------------------------------------
static __device__ void phaseA(int b, int t,
                              const float* __restrict__ hcur,
                              const float* __restrict__ x,
                              const float* __restrict__ mem,
                              const float* __restrict__ Wk,
                              const float* __restrict__ bk,
                              const float* __restrict__ Wri,
                              const float* __restrict__ bri,
                              float* sm)
{
    float* hs    = sm;           // 1024
    float* ex    = sm + 1024;    // 1024
    float* kq    = sm + 2048;    // 64
    float* red   = sm + 2112;    // 1024 (16 groups x 64)
    float* readv = sm + 3136;    // 64
    float* sred  = sm + 3200;    // 64

    const int tid  = threadIdx.x;
    const int warp = tid >> 5;    // 0..31
    const int lane = tid & 31;

    hs[tid] = hcur[b * HH + tid];
    __syncthreads();

    // kq[m] = h . Wk[m,:] + bk[m]   (32 warps x 2 rows)
    #pragma unroll
    for (int mi = 0; mi < 2; mi++) {
        int m = warp * 2 + mi;
        const float* wrow = Wk + (size_t)m * HH;
        float s = 0.f;
        for (int k = lane; k < HH; k += 32) s += hs[k] * wrow[k];
        #pragma unroll
        for (int off = 16; off; off >>= 1) s += __shfl_down_sync(0xffffffffu, s, off);
        if (lane == 0) kq[m] = s + bk[m];
    }
    __syncthreads();

    // one score per thread from transposed memory
    float s0 = 0.f;
    const float* mt = g_memT + tid;
    #pragma unroll 8
    for (int m = 0; m < MM; m++) s0 += kq[m] * mt[m * PP];
    float lmax = s0;
    #pragma unroll
    for (int off = 16; off; off >>= 1)
        lmax = fmaxf(lmax, __shfl_xor_sync(0xffffffffu, lmax, off));
    if (lane == 0) sred[warp] = lmax;
    __syncthreads();
    float bmax = sred[0];
    #pragma unroll
    for (int w = 1; w < 32; w++) bmax = fmaxf(bmax, sred[w]);

    float e0 = expf(s0 - bmax);
    ex[tid] = e0;
    float lsum = e0;
    #pragma unroll
    for (int off = 16; off; off >>= 1)
        lsum += __shfl_xor_sync(0xffffffffu, lsum, off);
    if (lane == 0) sred[32 + warp] = lsum;
    __syncthreads();
    float bsum = 0.f;
    #pragma unroll
    for (int w = 0; w < 32; w++) bsum += sred[32 + w];

    // read[m] = sum_p ex[p]*mem[p,m] / bsum  (16 p-groups of 64)
    {
        int m = tid & 63;
        int q = tid >> 6;                  // 0..15
        const float* mp = mem + (size_t)(q * 64) * MM + m;
        const float* ep = ex + q * 64;
        float pr = 0.f;
        #pragma unroll 4
        for (int p = 0; p < 64; p++) pr += ep[p] * mp[(size_t)p * MM];
        red[q * 64 + m] = pr;
    }
    __syncthreads();
    if (tid < MM) {
        float s = 0.f;
        #pragma unroll
        for (int q = 0; q < 16; q++) s += red[q * 64 + tid];
        readv[tid] = s / bsum;
    }
    __syncthreads();

    if (tid < II) {
        const float4* wr = (const float4*)(Wri + (size_t)tid * MM);
        float s = bri[tid];
        #pragma unroll
        for (int m4 = 0; m4 < 16; m4++) {
            float4 w = wr[m4];
            s += readv[m4 * 4 + 0] * w.x + readv[m4 * 4 + 1] * w.y
               + readv[m4 * 4 + 2] * w.z + readv[m4 * 4 + 3] * w.w;
        }
        g_xin[b * II + tid] = x[((size_t)b * TT + t) * II + tid] + fmaxf(s, 0.f);
    }
    __syncthreads();
}

// ---------------------------------------------------------------------------
// Persistent megakernel
// ---------------------------------------------------------------------------
__global__ void __launch_bounds__(NT, 1) ntm_persist(
    const float* __restrict__ x,    const float* __restrict__ mem,
    const float* __restrict__ Wk,   const float* __restrict__ bk,
    const float* __restrict__ Wri,  const float* __restrict__ bri,
    const float* __restrict__ Wih,  const float* __restrict__ Whh,
    const float* __restrict__ bih,  const float* __restrict__ bhh,
    const float* __restrict__ Wout, const float* __restrict__ bout,
    float* __restrict__ out)
{
    extern __shared__ __align__(16) float smf[];      // 174,080 B
    const uint32_t sb = smem_u32(smf);

    const int bid = blockIdx.x;
    const int tid = threadIdx.x;
    const int gid = bid * NT + tid;

    for (int e = gid; e < BB * HH; e += NB * NT) g_h[0][e] = 0.f;
    for (int e = gid; e < PP * MM; e += NB * NT) {
        int p = e >> 6, m = e & 63;
        g_memT[m * PP + p] = mem[e];
    }
    gsync();

    for (int t = 0; t <= TT; t++) {
        const float* hcur = g_h[t & 1];

        // slot1: phaseA(t) [0..31, 2 rows each] || out GEMM(t-1) [32..47]
        //        || gh(t) [48..143]
        if (t < TT && bid < 32) {
            phaseA(bid * 2,     t, hcur, x, mem, Wk, bk, Wri, bri, smf);
            phaseA(bid * 2 + 1, t, hcur, x, mem, Wk, bk, Wri, bri, smf);
        } else if (t >= 1 && bid >= 32 && bid < 48) {
            int j = bid - 32, ct = j >> 3, ks = j & 7;    // 2 ct x 8 ks(128)
            gemm256(Wout + (size_t)(ct * 256) * HH + ks * 128, HH,
                    hcur + ks * 128, HH, 2, g_cp[ks], OO, ct * 256, smf, sb);
        } else if (t < TT && bid >= 48 && bid < 144) {
            int j = bid - 48, ct = j >> 3, ks = j & 7;    // 12 ct x 8 ks(128)
            gemm256(Whh + (size_t)(ct * 256) * HH + ks * 128, HH,
                    hcur + ks * 128, HH, 2, g_gh[ks], G3, ct * 256, smf, sb);
        }
        gsync();

        // slot2: gi(t) [0..95] || out combine(t-1) [96..99]
        if (t < TT && bid < 96) {
            int ct = bid >> 3, ks = bid & 7;              // 12 ct x 8 ks(64)
            gemm256(Wih + (size_t)(ct * 256) * II + ks * 64, II,
                    g_xin + ks * 64, II, 1, g_gi[ks], G3, ct * 256, smf, sb);
        } else if (t >= 1 && bid >= 96 && bid < 100) {
            int idx = (bid - 96) * NT + tid;              // 0..4095
            for (int e = idx; e < BB * OO; e += 4 * NT) {
                int b = e >> 9, oc = e & (OO - 1);
                float s = bout[oc];
                #pragma unroll
                for (int q = 0; q < 8; q++) s += g_cp[q][e];
                out[((size_t)b * TT + (t - 1)) * OO + oc] = 1.f / (1.f + expf(-s));
            }
        }
        if (t == TT) break;
        gsync();

        // slot3: GRU combine -> h(t+1)
        if (gid < BB * HH) {
            float* hnew = g_h[(t + 1) & 1];
            int b = gid >> 10, c = gid & 1023;
            size_t o = (size_t)b * G3 + c;
            float ir = bih[c], iz = bih[1024 + c], inn = bih[2048 + c];
            #pragma unroll
            for (int q = 0; q < 8; q++) {
                ir  += g_gi[q][o];
                iz  += g_gi[q][o + 1024];
                inn += g_gi[q][o + 2048];
            }
            float hr = bhh[c], hz = bhh[1024 + c], hn = bhh[2048 + c];
            #pragma unroll
            for (int q = 0; q < 8; q++) {
                hr += g_gh[q][o];
                hz += g_gh[q][o + 1024];
                hn += g_gh[q][o + 2048];
            }
            float rg = 1.f / (1.f + expf(-(ir + hr)));
            float zg = 1.f / (1.f + expf(-(iz + hz)));
            float ng = tanhf(inn + rg * hn);
            hnew[gid] = (1.f - zg) * ng + zg * hcur[gid];
        }
        gsync();
    }
}

extern "C" void kernel_launch(void* const* d_in, const int* in_sizes, int n_in,
                              void* d_out, int out_size)
{
    const float* x    = (const float*)d_in[0];
    const float* mem  = (const float*)d_in[1];
    const float* Wk   = (const float*)d_in[2];
    const float* bk   = (const float*)d_in[3];
    const float* Wri  = (const float*)d_in[4];
    const float* bri  = (const float*)d_in[5];
    const float* Wih  = (const float*)d_in[6];
    const float* Whh  = (const float*)d_in[7];
    const float* bih  = (const float*)d_in[8];
    const float* bhh  = (const float*)d_in[9];
    const float* Wout = (const float*)d_in[10];
    const float* bout = (const float*)d_in[11];

    static int once = 0;
    const int smem_bytes = 2 * BUFF * 4;   // 174,080
    if (!once) {
        cudaFuncSetAttribute(ntm_persist,
                             cudaFuncAttributeMaxDynamicSharedMemorySize,
                             smem_bytes);
        once = 1;
    }

    ntm_persist<<<NB, NT, smem_bytes>>>(x, mem, Wk, bk, Wri, bri, Wih, Whh,
                                        bih, bhh, Wout, bout, (float*)d_out);
}